// round 17
// baseline (speedup 1.0000x reference)
#include <cuda_runtime.h>
#include <cuda_fp16.h>
#include <math.h>
#include <stdint.h>

#define KST 3
#define NN 30000
#define NE 300000
#define FIN 256
#define FHID 256
#define FOUT 64
#define KP1 (FIN / 2)    // 128
#define KPH (FHID / 2)   // 128
#define KPO (FOUT / 2)   // 32

// ---------------- scratch (device globals) ------------------------------------
__device__ __align__(16) uint32_t g_X[NN * KP1];
__device__ __align__(16) uint32_t g_H0[KST * NN * KPH];
__device__ __align__(16) uint32_t g_H1[KST * NN * KPH];
__device__ __align__(16) uint32_t g_R1[KST * NN * KPH];
__device__ __align__(16) uint32_t g_HM[NN * KPH];
__device__ __align__(16) uint32_t g_G0[KST * NN * KPO];
__device__ __align__(16) uint32_t g_G1[KST * NN * KPO];
__device__ __align__(16) uint32_t g_R2[KST * NN * KPO];
__device__ __align__(16) uint32_t g_W1C[KST * 512 * KP1];
__device__ __align__(16) uint32_t g_W1[KST * 256 * KPH];
__device__ __align__(16) uint32_t g_W2C[KST * 128 * KPH];
__device__ __align__(16) uint32_t g_W2[KST * 64 * KPO];
__device__ float g_dis[NN];
__device__ int g_cnt[NN];
__device__ int g_rowptr[NN + 1];
__device__ int g_cursor[NN];
__device__ int g_src[NE];
__device__ float g_nrm[NE];
__device__ int g_is64;
#define SCAN_NBLK 118
__device__ int g_bsum[SCAN_NBLK + 1];

// ---------------- helpers -----------------------------------------------------
__device__ __forceinline__ uint32_t pack_f16(float a, float b) {
    __half2 h = __floats2half2_rn(a, b);
    return *reinterpret_cast<uint32_t*>(&h);
}

__device__ __forceinline__ float2 h2f2(uint32_t u) {
    __half2 h = *reinterpret_cast<__half2*>(&u);
    return __half22float2(h);
}

__device__ __forceinline__ void mma_f16(float* c, const uint32_t* a, const uint32_t* bb) {
    asm volatile(
        "mma.sync.aligned.m16n8k16.row.col.f32.f16.f16.f32 "
        "{%0,%1,%2,%3}, {%4,%5,%6,%7}, {%8,%9}, {%0,%1,%2,%3};\n"
        : "+f"(c[0]), "+f"(c[1]), "+f"(c[2]), "+f"(c[3])
        : "r"(a[0]), "r"(a[1]), "r"(a[2]), "r"(a[3]), "r"(bb[0]), "r"(bb[1]));
}

__device__ __forceinline__ void ldsm4(uint32_t* r, uint32_t addr) {
    asm volatile("ldmatrix.sync.aligned.m8n8.x4.shared.b16 {%0,%1,%2,%3}, [%4];"
                 : "=r"(r[0]), "=r"(r[1]), "=r"(r[2]), "=r"(r[3])
                 : "r"(addr));
}

__device__ __forceinline__ void cpasync16(uint32_t dst, const uint32_t* src) {
    asm volatile("cp.async.cg.shared.global [%0], [%1], 16;" ::"r"(dst), "l"(src));
}

__device__ __forceinline__ void acc8(float* a, uint4 v, float w) {
    float2 f0 = h2f2(v.x), f1 = h2f2(v.y), f2 = h2f2(v.z), f3 = h2f2(v.w);
    a[0] += w * f0.x; a[1] += w * f0.y;
    a[2] += w * f1.x; a[3] += w * f1.y;
    a[4] += w * f2.x; a[5] += w * f2.y;
    a[6] += w * f3.x; a[7] += w * f3.y;
}

__device__ __forceinline__ void add8(float* a, uint4 v) {
    float2 f0 = h2f2(v.x), f1 = h2f2(v.y), f2 = h2f2(v.z), f3 = h2f2(v.w);
    a[0] += f0.x; a[1] += f0.y;
    a[2] += f1.x; a[3] += f1.y;
    a[4] += f2.x; a[5] += f2.y;
    a[6] += f3.x; a[7] += f3.y;
}

// ---------------- fused prep ---------------------------------------------------
__device__ __forceinline__ void wconv(const float* __restrict__ W, uint32_t* oh,
                                      int Kd, int N, int nOff, int outN, long idx) {
    int Kp = Kd / 2;
    int k = (int)(idx / ((long)N * Kp));
    int rem = (int)(idx % ((long)N * Kp));
    int n = rem / Kp;
    int kp = rem % Kp;
    const float* Wk = W + (long)k * Kd * N;
    float v0 = Wk[(long)(2 * kp) * N + n];
    float v1 = Wk[(long)(2 * kp + 1) * N + n];
    oh[((long)k * outN + nOff + n) * Kp + kp] = pack_f16(v0, v1);
}

#define CNT_X ((long)NN * KP1)
#define CNT_A (KST * 256 * 128)
#define CNT_B (KST * 64 * 128)
#define CNT_C (KST * 64 * 32)
#define CNT_PREP (CNT_X + 3 * CNT_A + 2 * CNT_B + CNT_C + NN)

__global__ void prep_kernel(const float* x, const float* iw1, const float* rw1,
                            const float* w1, const float* iw2, const float* rw2,
                            const float* w2, const int* ei_raw) {
    long id = blockIdx.x * 256L + threadIdx.x;
    if (id == 0) {
        int all_zero = 1;
        for (int j = 0; j < 128; j++)
            if (ei_raw[2 * j + 1] != 0) { all_zero = 0; break; }
        g_is64 = all_zero;
    }
    if (id < CNT_X) {
        float2 v = *(const float2*)(x + 2 * id);
        g_X[id] = pack_f16(v.x, v.y);
        return;
    }
    id -= CNT_X;
    if (id < CNT_A) { wconv(iw1, g_W1C, 256, 256, 0, 512, id); return; }
    id -= CNT_A;
    if (id < CNT_A) { wconv(rw1, g_W1C, 256, 256, 256, 512, id); return; }
    id -= CNT_A;
    if (id < CNT_A) { wconv(w1, g_W1, 256, 256, 0, 256, id); return; }
    id -= CNT_A;
    if (id < CNT_B) { wconv(iw2, g_W2C, 256, 64, 0, 128, id); return; }
    id -= CNT_B;
    if (id < CNT_B) { wconv(rw2, g_W2C, 256, 64, 64, 128, id); return; }
    id -= CNT_B;
    if (id < CNT_C) { wconv(w2, g_W2, 64, 64, 0, 64, id); return; }
    id -= CNT_C;
    if (id < NN) g_cnt[id] = 0;
}

// ---------------- CSR ----------------------------------------------------------
__device__ __forceinline__ int load_idx(const void* ei, long pos) {
    if (g_is64) return (int)((const long long*)ei)[pos];
    return ((const int*)ei)[pos];
}

__global__ void count_deg_kernel(const void* __restrict__ ei) {
    int e = blockIdx.x * blockDim.x + threadIdx.x;
    if (e < NE) {
        int c = load_idx(ei, (long)NE + e);
        if (c >= 0 && c < NN) atomicAdd(&g_cnt[c], 1);
    }
}

__global__ void scan1_kernel() {
    __shared__ int sh[256];
    int blk = blockIdx.x;
    int i = blk * 256 + threadIdx.x;
    int v = (i < NN) ? g_cnt[i] : 0;
    if (i < NN) g_dis[i] = (v > 0) ? rsqrtf((float)v) : 0.0f;
    sh[threadIdx.x] = v;
    __syncthreads();
    for (int d = 1; d < 256; d <<= 1) {
        int t = (threadIdx.x >= (unsigned)d) ? sh[threadIdx.x - d] : 0;
        __syncthreads();
        sh[threadIdx.x] += t;
        __syncthreads();
    }
    int incl = sh[threadIdx.x];
    if (i < NN) g_rowptr[i] = incl - v;
    if (threadIdx.x == 255) g_bsum[blk] = incl;
}

__global__ void scan3_kernel() {
    __shared__ int sh[128];
    int tid = threadIdx.x;
    if (tid < 128) sh[tid] = (tid < SCAN_NBLK) ? g_bsum[tid] : 0;
    __syncthreads();
    for (int d = 1; d < 128; d <<= 1) {
        int t = (tid < 128 && tid >= d) ? sh[tid - d] : 0;
        __syncthreads();
        if (tid < 128) sh[tid] += t;
        __syncthreads();
    }
    int prefix = sh[blockIdx.x] - g_bsum[blockIdx.x];
    int i = blockIdx.x * 256 + tid;
    if (i < NN) {
        int ex = g_rowptr[i] + prefix;
        g_rowptr[i] = ex;
        g_cursor[i] = ex;
    }
    if (blockIdx.x == 0 && tid == 0) g_rowptr[NN] = sh[SCAN_NBLK - 1];
}

__global__ void fill_csr_kernel(const void* __restrict__ ei) {
    int e = blockIdx.x * blockDim.x + threadIdx.x;
    if (e < NE) {
        int r = load_idx(ei, e);
        int c = load_idx(ei, (long)NE + e);
        if (r >= 0 && r < NN && c >= 0 && c < NN) {
            int pos = atomicAdd(&g_cursor[c], 1);
            if (pos >= 0 && pos < NE) {
                g_src[pos] = r;
                g_nrm[pos] = g_dis[r] * g_dis[c];
            }
        }
    }
}

// ---------------- fp16 tensor-core GEMM ----------------------------------------
#define APITCH 20
#define NSTAGE 4
#define A_PLANE 10240
#define B_OFF (NSTAGE * A_PLANE)

template <int BN>
__global__ void __launch_bounds__(256, (BN == 128) ? 2 : 3)
bgemm2(const uint32_t* __restrict__ A,
       const uint32_t* __restrict__ B,
       const float* __restrict__ bias,
       uint32_t* __restrict__ C0,
       uint32_t* __restrict__ C1,
       int M, int Ntot, int N1, int Kd) {
    constexpr int MT = (BN == 128) ? 4 : 2;
    constexpr int B_PLANE = BN * APITCH * 4;
    extern __shared__ uint32_t smem[];
    uint32_t smem_u = (uint32_t)__cvta_generic_to_shared(smem);
    int Kp = Kd >> 1;
    int bm = blockIdx.y * 128, bn = blockIdx.x * BN;
    int tid = threadIdx.x, warp = tid >> 5, lane = tid & 31;
    int g = lane >> 2, t = lane & 3;
    int wm, wn;
    if (BN == 128) { wm = warp >> 2; wn = warp & 3; }
    else           { wm = warp >> 1; wn = warp & 1; }

    int rowL = tid >> 2, segL = tid & 3;
    int gm0 = bm + rowL;       if (gm0 >= M) gm0 = M - 1;
    int gm1 = bm + rowL + 64;  if (gm1 >= M) gm1 = M - 1;
    const uint32_t* sA0 = A + (long)gm0 * Kp + segL * 4;
    const uint32_t* sA1 = A + (long)gm1 * Kp + segL * 4;
    const uint32_t* sB0 = B + (long)(bn + rowL) * Kp + segL * 4;
    const uint32_t* sB1 = sB0 + (long)64 * Kp;
    uint32_t dA0 = smem_u + (rowL * APITCH + segL * 4) * 4;
    uint32_t dA1 = dA0 + 64 * APITCH * 4;
    uint32_t dB0 = smem_u + B_OFF + (rowL * APITCH + segL * 4) * 4;
    uint32_t dB1 = dB0 + 64 * APITCH * 4;

    int rowA = ((lane >> 3) & 1) * 8 + (lane & 7);
    int segA = (lane >> 4) * 4;
    int rowB = ((lane >> 4) & 1) * 8 + (lane & 7);
    int segB = ((lane >> 3) & 1) * 4;
    uint32_t aOff0 = smem_u + ((wm * (MT * 16) + rowA) * APITCH + segA) * 4;
    uint32_t bOff0 = smem_u + B_OFF + ((wn * 32 + rowB) * APITCH + segB) * 4;
    uint32_t bOff1 = bOff0 + 16 * APITCH * 4;

    auto issue = [&](int kt) {
        uint32_t aD = kt * (uint32_t)A_PLANE;
        uint32_t bD = kt * (uint32_t)B_PLANE;
        cpasync16(dA0 + aD, sA0);
        cpasync16(dA1 + aD, sA1);
        cpasync16(dB0 + bD, sB0);
        if (BN == 128) cpasync16(dB1 + bD, sB1);
        sA0 += 16;
        sA1 += 16;
        sB0 += 16;
        if (BN == 128) sB1 += 16;
        asm volatile("cp.async.commit_group;" ::: "memory");
    };

    float acc[MT][4][4];
#pragma unroll
    for (int i = 0; i < MT; i++)
#pragma unroll
        for (int j = 0; j < 4; j++)
#pragma unroll
            for (int k = 0; k < 4; k++) acc[i][j][k] = 0.f;

    int NT = Kd / 32;
    for (int s = 0; s < 3 && s < NT; s++) issue(s & 3);
    for (int kt = 0; kt < NT; kt++) {
        int buf = kt & 3;
        int rem = NT - kt;
        if (rem >= 3) {
            asm volatile("cp.async.wait_group 2;" ::: "memory");
        } else if (rem == 2) {
            asm volatile("cp.async.wait_group 1;" ::: "memory");
        } else {
            asm volatile("cp.async.wait_group 0;" ::: "memory");
        }
        __syncthreads();
        if (kt + 3 < NT) issue((kt + 3) & 3);
        uint32_t aBase = buf * (uint32_t)A_PLANE;
        uint32_t bBase = buf * (uint32_t)B_PLANE;
#pragma unroll
        for (int ks = 0; ks < 2; ks++) {
            uint32_t ko = ks * 32;
            uint32_t af[MT][4], bf[4][2];
#pragma unroll
            for (int mt = 0; mt < MT; mt++)
                ldsm4(af[mt], aOff0 + mt * (16 * APITCH * 4) + aBase + ko);
            ldsm4(&bf[0][0], bOff0 + bBase + ko);
            ldsm4(&bf[2][0], bOff1 + bBase + ko);
#pragma unroll
            for (int mt = 0; mt < MT; mt++)
#pragma unroll
                for (int nt = 0; nt < 4; nt++) mma_f16(acc[mt][nt], af[mt], bf[nt]);
        }
    }

    int row0 = bm + wm * (MT * 16);
    int col0 = bn + wn * 32;
#pragma unroll
    for (int nt = 0; nt < 4; nt++) {
        int c = col0 + nt * 8 + 2 * t;
        bool out1 = (c >= N1);
        float bx = 0.f, by = 0.f;
        uint32_t* O;
        long pitch;
        int cc;
        if (out1) {
            if (bias) {
                bx = bias[c - N1];
                by = bias[c - N1 + 1];
            }
            O = C1;
            pitch = (Ntot - N1) >> 1;
            cc = (c - N1) >> 1;
        } else {
            O = C0;
            pitch = N1 >> 1;
            cc = c >> 1;
        }
#pragma unroll
        for (int mt = 0; mt < MT; mt++) {
            int r = row0 + mt * 16 + g;
            if (r < M)
                O[(long)r * pitch + cc] = pack_f16(acc[mt][nt][0] + bx, acc[mt][nt][1] + by);
            if (r + 8 < M)
                O[(long)(r + 8) * pitch + cc] =
                    pack_f16(acc[mt][nt][2] + bx, acc[mt][nt][3] + by);
        }
    }
}

#define GSMEM128 (NSTAGE * (A_PLANE + 128 * APITCH * 4))  // 81920
#define GSMEM64 (NSTAGE * (A_PLANE + 64 * APITCH * 4))    // 61440

// ---------------- prop (per-stack, uint4 gather, 2-edge interleave) -------------
template <int F, bool RELU>
__global__ void prop_kernel(const uint32_t* __restrict__ H,
                            const uint32_t* __restrict__ R,
                            uint32_t* __restrict__ O) {
    constexpr int LANES = F / 8;
    constexpr int NPB = 256 / LANES;
    constexpr int PITCH = F / 2;
    int lane = threadIdx.x % LANES;
    int local = threadIdx.x / LANES;
    int n = blockIdx.x * NPB + local;
    if (n >= NN) return;
    int e0 = g_rowptr[n], e1 = g_rowptr[n + 1];
    float a[8] = {0.f, 0.f, 0.f, 0.f, 0.f, 0.f, 0.f, 0.f};
    int e = e0;
#pragma unroll 2
    for (; e + 1 < e1; e += 2) {
        int s0 = g_src[e], s1 = g_src[e + 1];
        float w0 = g_nrm[e], w1 = g_nrm[e + 1];
        uint4 v0 = *(const uint4*)(H + (long)s0 * PITCH + lane * 4);
        uint4 v1 = *(const uint4*)(H + (long)s1 * PITCH + lane * 4);
        acc8(a, v0, w0);
        acc8(a, v1, w1);
    }
    if (e < e1) {
        int s = g_src[e];
        float w = g_nrm[e];
        uint4 v = *(const uint4*)(H + (long)s * PITCH + lane * 4);
        acc8(a, v, w);
    }
    long off = (long)n * PITCH + lane * 4;
    add8(a, *(const uint4*)(R + off));
    if (RELU) {
#pragma unroll
        for (int j = 0; j < 8; j++) a[j] = fmaxf(a[j], 0.f);
    }
    uint4 o;
    o.x = pack_f16(a[0], a[1]);
    o.y = pack_f16(a[2], a[3]);
    o.z = pack_f16(a[4], a[5]);
    o.w = pack_f16(a[6], a[7]);
    *(uint4*)(O + off) = o;
}

// ---------------- first conv1 prop, all stacks (6-gather interleave) ------------
__global__ void prop1_all_kernel(const uint32_t* __restrict__ H,
                                 const uint32_t* __restrict__ R,
                                 uint32_t* __restrict__ O) {
    int lane = threadIdx.x & 31;
    int local = threadIdx.x >> 5;
    int n = blockIdx.x * 8 + local;
    if (n >= NN) return;
    int e0 = g_rowptr[n], e1 = g_rowptr[n + 1];
    float a[KST][8];
#pragma unroll
    for (int k = 0; k < KST; k++)
#pragma unroll
        for (int j = 0; j < 8; j++) a[k][j] = 0.f;
    const long P1 = (long)NN * KPH, P2 = 2L * NN * KPH;
    int e = e0;
    for (; e + 1 < e1; e += 2) {
        int s0 = g_src[e], s1 = g_src[e + 1];
        float w0 = g_nrm[e], w1 = g_nrm[e + 1];
        long so0 = (long)s0 * KPH + lane * 4;
        long so1 = (long)s1 * KPH + lane * 4;
        uint4 u0 = *(const uint4*)(H + so0);
        uint4 u1 = *(const uint4*)(H + P1 + so0);
        uint4 u2 = *(const uint4*)(H + P2 + so0);
        uint4 u3 = *(const uint4*)(H + so1);
        uint4 u4 = *(const uint4*)(H + P1 + so1);
        uint4 u5 = *(const uint4*)(H + P2 + so1);
        acc8(a[0], u0, w0);
        acc8(a[1], u1, w0);
        acc8(a[2], u2, w0);
        acc8(a[0], u3, w1);
        acc8(a[1], u4, w1);
        acc8(a[2], u5, w1);
    }
    if (e < e1) {
        int s = g_src[e];
        float w = g_nrm[e];
        long so = (long)s * KPH + lane * 4;
        acc8(a[0], *(const uint4*)(H + so), w);
        acc8(a[1], *(const uint4*)(H + P1 + so), w);
        acc8(a[2], *(const uint4*)(H + P2 + so), w);
    }
    long ro = (long)n * KPH + lane * 4;
#pragma unroll
    for (int k = 0; k < KST; k++) {
        add8(a[k], *(const uint4*)(R + (long)k * P1 + ro));
        uint4 o;
        o.x = pack_f16(fmaxf(a[k][0], 0.f), fmaxf(a[k][1], 0.f));
        o.y = pack_f16(fmaxf(a[k][2], 0.f), fmaxf(a[k][3], 0.f));
        o.z = pack_f16(fmaxf(a[k][4], 0.f), fmaxf(a[k][5], 0.f));
        o.w = pack_f16(fmaxf(a[k][6], 0.f), fmaxf(a[k][7], 0.f));
        *(uint4*)(O + (long)k * P1 + ro) = o;
    }
}

// ---------------- fused 2nd conv1 prop + mean (6-gather interleave) -------------
__global__ void prop1_mean_kernel(const uint32_t* __restrict__ H,
                                  const uint32_t* __restrict__ R) {
    int lane = threadIdx.x & 31;
    int local = threadIdx.x >> 5;
    int n = blockIdx.x * 8 + local;
    if (n >= NN) return;
    int e0 = g_rowptr[n], e1 = g_rowptr[n + 1];
    float a[KST][8];
#pragma unroll
    for (int k = 0; k < KST; k++)
#pragma unroll
        for (int j = 0; j < 8; j++) a[k][j] = 0.f;
    const long P1 = (long)NN * KPH, P2 = 2L * NN * KPH;
    int e = e0;
    for (; e + 1 < e1; e += 2) {
        int s0 = g_src[e], s1 = g_src[e + 1];
        float w0 = g_nrm[e], w1 = g_nrm[e + 1];
        long so0 = (long)s0 * KPH + lane * 4;
        long so1 = (long)s1 * KPH + lane * 4;
        uint4 u0 = *(const uint4*)(H + so0);
        uint4 u1 = *(const uint4*)(H + P1 + so0);
        uint4 u2 = *(const uint4*)(H + P2 + so0);
        uint4 u3 = *(const uint4*)(H + so1);
        uint4 u4 = *(const uint4*)(H + P1 + so1);
        uint4 u5 = *(const uint4*)(H + P2 + so1);
        acc8(a[0], u0, w0);
        acc8(a[1], u1, w0);
        acc8(a[2], u2, w0);
        acc8(a[0], u3, w1);
        acc8(a[1], u4, w1);
        acc8(a[2], u5, w1);
    }
    if (e < e1) {
        int s = g_src[e];
        float w = g_nrm[e];
        long so = (long)s * KPH + lane * 4;
        acc8(a[0], *(const uint4*)(H + so), w);
        acc8(a[1], *(const uint4*)(H + P1 + so), w);
        acc8(a[2], *(const uint4*)(H + P2 + so), w);
    }
    long ro = (long)n * KPH + lane * 4;
    float m[8] = {0.f, 0.f, 0.f, 0.f, 0.f, 0.f, 0.f, 0.f};
#pragma unroll
    for (int k = 0; k < KST; k++) {
        add8(a[k], *(const uint4*)(R + (long)k * P1 + ro));
#pragma unroll
        for (int j = 0; j < 8; j++) m[j] += fmaxf(a[k][j], 0.f);
    }
    uint4 o;
    o.x = pack_f16(m[0] * (1.f / 3.f), m[1] * (1.f / 3.f));
    o.y = pack_f16(m[2] * (1.f / 3.f), m[3] * (1.f / 3.f));
    o.z = pack_f16(m[4] * (1.f / 3.f), m[5] * (1.f / 3.f));
    o.w = pack_f16(m[6] * (1.f / 3.f), m[7] * (1.f / 3.f));
    *(uint4*)(g_HM + ro) = o;
}

// ---------------- fused 2nd conv2 prop + mean + log_softmax ---------------------
__global__ void prop2_final_kernel(const uint32_t* __restrict__ H,
                                   const uint32_t* __restrict__ R,
                                   float* __restrict__ out) {
    int lane = threadIdx.x & 7;
    int local = threadIdx.x >> 3;
    int n = blockIdx.x * 32 + local;
    if (n >= NN) return;
    int e0 = g_rowptr[n], e1 = g_rowptr[n + 1];
    float a[KST][8];
#pragma unroll
    for (int k = 0; k < KST; k++)
#pragma unroll
        for (int j = 0; j < 8; j++) a[k][j] = 0.f;
    const long P1 = (long)NN * KPO, P2 = 2L * NN * KPO;
    int e = e0;
    for (; e + 1 < e1; e += 2) {
        int s0 = g_src[e], s1 = g_src[e + 1];
        float w0 = g_nrm[e], w1 = g_nrm[e + 1];
        long so0 = (long)s0 * KPO + lane * 4;
        long so1 = (long)s1 * KPO + lane * 4;
        uint4 u0 = *(const uint4*)(H + so0);
        uint4 u1 = *(const uint4*)(H + P1 + so0);
        uint4 u2 = *(const uint4*)(H + P2 + so0);
        uint4 u3 = *(const uint4*)(H + so1);
        uint4 u4 = *(const uint4*)(H + P1 + so1);
        uint4 u5 = *(const uint4*)(H + P2 + so1);
        acc8(a[0], u0, w0);
        acc8(a[1], u1, w0);
        acc8(a[2], u2, w0);
        acc8(a[0], u3, w1);
        acc8(a[1], u4, w1);
        acc8(a[2], u5, w1);
    }
    if (e < e1) {
        int s = g_src[e];
        float w = g_nrm[e];
        long so = (long)s * KPO + lane * 4;
        acc8(a[0], *(const uint4*)(H + so), w);
        acc8(a[1], *(const uint4*)(H + P1 + so), w);
        acc8(a[2], *(const uint4*)(H + P2 + so), w);
    }
    long ro = (long)n * KPO + lane * 4;
    float m[8] = {0.f, 0.f, 0.f, 0.f, 0.f, 0.f, 0.f, 0.f};
#pragma unroll
    for (int k = 0; k < KST; k++) {
        add8(a[k], *(const uint4*)(R + (long)k * P1 + ro));
#pragma unroll
        for (int j = 0; j < 8; j++) m[j] += a[k][j];
    }
#pragma unroll
    for (int j = 0; j < 8; j++) m[j] *= (1.f / 3.f);
    float mx = m[0];
#pragma unroll
    for (int j = 1; j < 8; j++) mx = fmaxf(mx, m[j]);
#pragma unroll
    for (int d = 4; d; d >>= 1) mx = fmaxf(mx, __shfl_xor_sync(0xffffffffu, mx, d, 8));
    float s = 0.f;
#pragma unroll
    for (int j = 0; j < 8; j++) s += expf(m[j] - mx);
#pragma unroll
    for (int d = 4; d; d >>= 1) s += __shfl_xor_sync(0xffffffffu, s, d, 8);
    float lg = mx + logf(s);
    float* o = out + (long)n * FOUT + lane * 8;
#pragma unroll
    for (int j = 0; j < 8; j++) o[j] = m[j] - lg;
}

// ---------------- launch ---------------------------------------------------------
extern "C" void kernel_launch(void* const* d_in, const int* in_sizes, int n_in,
                              void* d_out, int out_size) {
    const float* x = (const float*)d_in[0];
    const void* ei = d_in[1];
    const float* init_w1 = (const float*)d_in[2];
    const float* w1 = (const float*)d_in[3];
    const float* root_w1 = (const float*)d_in[4];
    const float* bias1 = (const float*)d_in[5];
    const float* init_w2 = (const float*)d_in[6];
    const float* w2 = (const float*)d_in[7];
    const float* root_w2 = (const float*)d_in[8];
    const float* bias2 = (const float*)d_in[9];
    float* out = (float*)d_out;

    static bool init_done = false;
    static cudaStream_t sB, sC, sD;
    static cudaEvent_t ev0, evCSR, ev1, ev2, evP, evM, ev1b, ev2b;
    if (!init_done) {
        cudaFuncSetAttribute(bgemm2<128>, cudaFuncAttributeMaxDynamicSharedMemorySize,
                             GSMEM128);
        cudaFuncSetAttribute(bgemm2<64>, cudaFuncAttributeMaxDynamicSharedMemorySize,
                             GSMEM64);
        cudaStreamCreateWithFlags(&sB, cudaStreamNonBlocking);
        cudaStreamCreateWithFlags(&sC, cudaStreamNonBlocking);
        cudaStreamCreateWithFlags(&sD, cudaStreamNonBlocking);
        cudaEventCreateWithFlags(&ev0, cudaEventDisableTiming);
        cudaEventCreateWithFlags(&evCSR, cudaEventDisableTiming);
        cudaEventCreateWithFlags(&ev1, cudaEventDisableTiming);
        cudaEventCreateWithFlags(&ev2, cudaEventDisableTiming);
        cudaEventCreateWithFlags(&evP, cudaEventDisableTiming);
        cudaEventCreateWithFlags(&evM, cudaEventDisableTiming);
        cudaEventCreateWithFlags(&ev1b, cudaEventDisableTiming);
        cudaEventCreateWithFlags(&ev2b, cudaEventDisableTiming);
        init_done = true;
    }

    uint32_t *X, *H0, *H1, *R1, *HM, *G0, *G1, *R2;
    uint32_t *W1C, *W1, *W2C, *W2;
    cudaGetSymbolAddress((void**)&X, g_X);
    cudaGetSymbolAddress((void**)&H0, g_H0);
    cudaGetSymbolAddress((void**)&H1, g_H1);
    cudaGetSymbolAddress((void**)&R1, g_R1);
    cudaGetSymbolAddress((void**)&HM, g_HM);
    cudaGetSymbolAddress((void**)&G0, g_G0);
    cudaGetSymbolAddress((void**)&G1, g_G1);
    cudaGetSymbolAddress((void**)&R2, g_R2);
    cudaGetSymbolAddress((void**)&W1C, g_W1C);
    cudaGetSymbolAddress((void**)&W1, g_W1);
    cudaGetSymbolAddress((void**)&W2C, g_W2C);
    cudaGetSymbolAddress((void**)&W2, g_W2);

    const int MY = (NN + 127) / 128;  // 235
    cudaStream_t stk[3] = {0, sB, sC};

    prep_kernel<<<(int)((CNT_PREP + 255) / 256), 256>>>(
        x, init_w1, root_w1, w1, init_w2, root_w2, w2, (const int*)ei);
    cudaEventRecord(ev0, 0);
    cudaStreamWaitEvent(sB, ev0, 0);
    cudaStreamWaitEvent(sC, ev0, 0);
    cudaStreamWaitEvent(sD, ev0, 0);

    // CSR chain on sD (hidden under conv1 GEMMs)
    count_deg_kernel<<<(NE + 255) / 256, 256, 0, sD>>>(ei);
    scan1_kernel<<<SCAN_NBLK, 256, 0, sD>>>();
    scan3_kernel<<<SCAN_NBLK, 256, 0, sD>>>();
    fill_csr_kernel<<<(NE + 255) / 256, 256, 0, sD>>>(ei);
    cudaEventRecord(evCSR, sD);

    // per-stack conv1c GEMMs on 3 streams
    for (int k = 0; k < KST; k++) {
        long oH = (long)k * NN * KPH;
        bgemm2<128><<<dim3(4, MY), 256, GSMEM128, stk[k]>>>(
            X, W1C + (long)k * 512 * KP1, bias1 + k * FHID, H0 + oH, R1 + oH,
            NN, 512, 256, FIN);
    }
    cudaEventRecord(ev1, sB);
    cudaEventRecord(ev2, sC);
    cudaStreamWaitEvent(0, ev1, 0);
    cudaStreamWaitEvent(0, ev2, 0);
    cudaStreamWaitEvent(0, evCSR, 0);

    // first prop, all stacks fused (6 gathers in flight)
    prop1_all_kernel<<<(NN + 7) / 8, 256>>>(H0, R1, H1);
    cudaEventRecord(evP, 0);
    cudaStreamWaitEvent(sB, evP, 0);
    cudaStreamWaitEvent(sC, evP, 0);

    // per-stack gw1 GEMMs
    for (int k = 0; k < KST; k++) {
        long oH = (long)k * NN * KPH;
        bgemm2<128><<<dim3(2, MY), 256, GSMEM128, stk[k]>>>(
            H1 + oH, W1 + (long)k * 256 * KPH, nullptr, H0 + oH, nullptr,
            NN, 256, 256, FHID);
    }
    cudaEventRecord(ev1, sB);
    cudaEventRecord(ev2, sC);
    cudaStreamWaitEvent(0, ev1, 0);
    cudaStreamWaitEvent(0, ev2, 0);

    prop1_mean_kernel<<<(NN + 7) / 8, 256>>>(H0, R1);
    cudaEventRecord(evM, 0);
    cudaStreamWaitEvent(sB, evM, 0);
    cudaStreamWaitEvent(sC, evM, 0);

    // per-stack conv2 chains
    for (int k = 0; k < KST; k++) {
        cudaStream_t s = stk[k];
        long oG = (long)k * NN * KPO;
        bgemm2<128><<<dim3(1, MY), 256, GSMEM128, s>>>(
            HM, W2C + (long)k * 128 * KPH, bias2 + k * FOUT, G0 + oG, R2 + oG,
            NN, 128, 64, FHID);
        prop_kernel<FOUT, false><<<(NN + 31) / 32, 256, 0, s>>>(G0 + oG, R2 + oG, G1 + oG);
        bgemm2<64><<<dim3(1, MY), 256, GSMEM64, s>>>(
            G1 + oG, W2 + (long)k * 64 * KPO, nullptr, G0 + oG, nullptr,
            NN, 64, 64, FOUT);
    }
    cudaEventRecord(ev1b, sB);
    cudaEventRecord(ev2b, sC);
    cudaStreamWaitEvent(0, ev1b, 0);
    cudaStreamWaitEvent(0, ev2b, 0);

    prop2_final_kernel<<<(NN + 31) / 32, 256>>>(G0, R2, out);
}